// round 2
// baseline (speedup 1.0000x reference)
#include <cuda_runtime.h>
#include <math.h>
#include <stdint.h>

// Problem constants
#define CKD 64
#define QD 1620          // H*W = 30*54
#define OD 3
#define CVD 512
#define MD 32400
#define TOPK 20
#define CHD 1536         // OD*CVD

// K1 tiling
#define NCHUNK 6
#define CHUNK 5400       // MD / NCHUNK
#define QT 32            // q per K1 block
#define MT 256           // m tile per iteration
#define NQB 51           // ceil(QD/QT)
#define ITERS 22         // ceil(CHUNK/MT)

// K3 tiling
#define QT3 16

// ---------------- device scratch (static globals, no allocation) -------------
__device__ float g_asq8[MD];                       // 0.125 * ||mk_m||^2
__device__ float g_vt[(size_t)MD * CHD];           // transposed mem_v [M][1536]
__device__ float g_pval[NCHUNK * QD * TOPK];       // per-chunk partial topk vals
__device__ int   g_pidx[NCHUNK * QD * TOPK];       // per-chunk partial topk idx
__device__ float g_wval[QD * TOPK];                // softmax weights
__device__ int   g_widx[QD * TOPK];                // selected m indices

// ---------------- K0: a_sq precompute ---------------------------------------
__global__ void k_asq(const float* __restrict__ mk) {
    int m = blockIdx.x * 256 + threadIdx.x;
    if (m >= MD) return;
    float s = 0.f;
    #pragma unroll
    for (int c = 0; c < CKD; c++) {
        float v = mk[c * MD + m];
        s += v * v;
    }
    g_asq8[m] = s * 0.125f;
}

// ---------------- KT: transpose mem_v [1536][M] -> v_t [M][1536] -------------
__global__ void k_transpose(const float* __restrict__ v) {
    __shared__ float tile[32][33];
    int m0 = blockIdx.x * 32;
    int c0 = blockIdx.y * 32;
    int tx = threadIdx.x, ty = threadIdx.y;  // 32 x 8
    #pragma unroll
    for (int i = ty; i < 32; i += 8) {
        int m = m0 + tx;
        int c = c0 + i;
        tile[i][tx] = (m < MD) ? v[(size_t)c * MD + m] : 0.f;
    }
    __syncthreads();
    #pragma unroll
    for (int i = ty; i < 32; i += 8) {
        int m = m0 + i;
        int c = c0 + tx;
        if (m < MD) g_vt[(size_t)m * CHD + c] = tile[tx][i];
    }
}

// ---------------- K1: fused affinity GEMM + per-chunk top-20 -----------------
// grid: (NQB, NCHUNK), block: 256 threads, dynamic smem 108032 B
__global__ void __launch_bounds__(256, 2) k_aff_topk(
    const float* __restrict__ qk, const float* __restrict__ mk)
{
    extern __shared__ float smem[];
    float* mk_s  = smem;                       // 64*256 floats
    float* qk_s  = smem + CKD * MT;            // 64*32
    float* asq_s = qk_s + CKD * QT;            // 256
    float* aff_s = asq_s + MT;                 // 32*260 (padded rows)

    const int tid   = threadIdx.x;
    const int bq    = blockIdx.x;
    const int chunk = blockIdx.y;
    const int q0    = bq * QT;
    const int m_ch0 = chunk * CHUNK;
    const int m_end = m_ch0 + CHUNK;

    // load qk tile [64][32]
    for (int t = tid; t < CKD * QT; t += 256) {
        int c = t >> 5, j = t & 31;
        int q = q0 + j;
        qk_s[c * QT + j] = (q < QD) ? qk[c * QD + q] : 0.f;
    }

    const int tm = tid & 31, tq = tid >> 5;    // GEMM roles: 32 m-threads x 8 q-groups
    const int qown = tid >> 3, lane8 = tid & 7; // topk roles: 32 q-owners x 8 scanners

    float tkv[TOPK];
    int   tki[TOPK];
    #pragma unroll
    for (int i = 0; i < TOPK; i++) { tkv[i] = -3.0e38f; tki[i] = 0; }

    float4* mk4 = (float4*)mk_s;
    float4* qk4 = (float4*)qk_s;

    for (int it = 0; it < ITERS; it++) {
        const int m_base = m_ch0 + it * MT;

        // stage mk tile [64][256] (float4, coalesced) + asq
        for (int t = tid; t < CKD * (MT / 4); t += 256) {
            int c = t >> 6, f4 = t & 63;
            int mg = m_base + (f4 << 2);
            float4 val = make_float4(0.f, 0.f, 0.f, 0.f);
            if (mg < MD) val = *(const float4*)(mk + (size_t)c * MD + mg);
            mk4[(c << 6) + f4] = val;
        }
        {
            int mg = m_base + tid;
            asq_s[tid] = (mg < m_end) ? g_asq8[mg] : 1.0e37f;  // OOB -> aff ~ -1e37
        }
        __syncthreads();

        // register-tiled GEMM: 8 m x 4 q per thread over c=0..63
        float acc[8][4];
        #pragma unroll
        for (int i = 0; i < 8; i++) {
            #pragma unroll
            for (int j = 0; j < 4; j++) acc[i][j] = 0.f;
        }

        #pragma unroll 8
        for (int c = 0; c < CKD; c++) {
            float4 a0 = mk4[(c << 6) + tm];
            float4 a1 = mk4[(c << 6) + tm + 32];
            float4 qv = qk4[(c << 3) + tq];
            float am[8] = {a0.x, a0.y, a0.z, a0.w, a1.x, a1.y, a1.z, a1.w};
            float qm[4] = {qv.x, qv.y, qv.z, qv.w};
            #pragma unroll
            for (int i = 0; i < 8; i++) {
                #pragma unroll
                for (int j = 0; j < 4; j++) acc[i][j] += am[i] * qm[j];
            }
        }

        // affinity = 0.25*dot - 0.125*asq ; store to aff_s[q][m] (padded 260)
        #pragma unroll
        for (int jh = 0; jh < 2; jh++) {
            int ml = tm * 4 + jh * 128;
            #pragma unroll
            for (int jq = 0; jq < 4; jq++) {
                float4 v;
                v.x = acc[jh * 4 + 0][jq] * 0.25f - asq_s[ml + 0];
                v.y = acc[jh * 4 + 1][jq] * 0.25f - asq_s[ml + 1];
                v.z = acc[jh * 4 + 2][jq] * 0.25f - asq_s[ml + 2];
                v.w = acc[jh * 4 + 3][jq] * 0.25f - asq_s[ml + 3];
                *(float4*)(aff_s + (tq * 4 + jq) * 260 + ml) = v;
            }
        }
        __syncthreads();

        // streaming per-thread top-20 (sorted desc, bubble insert)
        const float* arow = aff_s + qown * 260;
        #pragma unroll 4
        for (int jj = 0; jj < 32; jj++) {
            int ml = lane8 + jj * 8;
            float v = arow[ml];
            if (v > tkv[TOPK - 1]) {
                int mg = m_base + ml;
                #pragma unroll
                for (int i = 0; i < TOPK; i++) {
                    if (v > tkv[i]) {
                        float t1 = tkv[i]; tkv[i] = v; v = t1;
                        int   t2 = tki[i]; tki[i] = mg; mg = t2;
                    }
                }
            }
        }
        __syncthreads();
    }

    // merge 8 sorted per-thread lists per q -> chunk-partial top-20
    float* mval = smem;                               // reuse mk_s region (40KB)
    int*   midx = (int*)(smem + QT * 8 * TOPK);
    {
        int base = (qown * 8 + lane8) * TOPK;
        #pragma unroll
        for (int i = 0; i < TOPK; i++) { mval[base + i] = tkv[i]; midx[base + i] = tki[i]; }
    }
    __syncthreads();

    if (tid < QT) {
        int q = q0 + tid;
        if (q < QD) {
            int cur[8] = {0, 0, 0, 0, 0, 0, 0, 0};
            int obase = (chunk * QD + q) * TOPK;
            for (int r = 0; r < TOPK; r++) {
                float best = -3.3e38f;
                int bt = 0;
                #pragma unroll
                for (int t = 0; t < 8; t++) {
                    float v = (cur[t] < TOPK) ? mval[(tid * 8 + t) * TOPK + cur[t]] : -3.4e38f;
                    if (v > best) { best = v; bt = t; }
                }
                g_pval[obase + r] = best;
                g_pidx[obase + r] = midx[(tid * 8 + bt) * TOPK + cur[bt]];
                cur[bt]++;
            }
        }
    }
}

// ---------------- K2: merge chunk partials + softmax -------------------------
__global__ void k_merge_softmax() {
    int q = blockIdx.x * 256 + threadIdx.x;
    if (q >= QD) return;
    int cur[NCHUNK] = {0, 0, 0, 0, 0, 0};
    float vals[TOPK];
    int   idxs[TOPK];
    for (int r = 0; r < TOPK; r++) {
        float best = -3.3e38f;
        int bc = 0;
        #pragma unroll
        for (int c = 0; c < NCHUNK; c++) {
            if (cur[c] < TOPK) {
                float v = g_pval[(c * QD + q) * TOPK + cur[c]];
                if (v > best) { best = v; bc = c; }
            }
        }
        vals[r] = best;
        idxs[r] = g_pidx[(bc * QD + q) * TOPK + cur[bc]];
        cur[bc]++;
    }
    float mx = vals[0];                 // merged list is descending
    float s = 0.f;
    #pragma unroll
    for (int r = 0; r < TOPK; r++) { vals[r] = expf(vals[r] - mx); s += vals[r]; }
    float inv = 1.f / s;
    #pragma unroll
    for (int r = 0; r < TOPK; r++) {
        g_wval[q * TOPK + r] = vals[r] * inv;
        g_widx[q * TOPK + r] = idxs[r];
    }
}

// ---------------- K3: sparse readout (coalesced gather on v_t) ---------------
// grid: (ceil(Q/16), 1536/256), block 256. Reads along channels, writes along q.
__global__ void k_readout(float* __restrict__ out) {
    __shared__ float sw[QT3 * TOPK];
    __shared__ int   si[QT3 * TOPK];
    int q0 = blockIdx.x * QT3;
    int ch = blockIdx.y * 256 + threadIdx.x;
    for (int t = threadIdx.x; t < QT3 * TOPK; t += 256) {
        int q = q0 + t / TOPK;
        if (q < QD) {
            sw[t] = g_wval[q * TOPK + (t % TOPK)];
            si[t] = g_widx[q * TOPK + (t % TOPK)];
        } else {
            sw[t] = 0.f;
            si[t] = 0;
        }
    }
    __syncthreads();

    float acc[QT3];
    #pragma unroll
    for (int j = 0; j < QT3; j++) acc[j] = 0.f;

    #pragma unroll
    for (int k = 0; k < TOPK; k++) {
        #pragma unroll
        for (int j = 0; j < QT3; j++) {   // 16 independent coalesced loads in flight
            float w = sw[j * TOPK + k];
            int   m = si[j * TOPK + k];
            acc[j] += w * g_vt[(size_t)m * CHD + ch];
        }
    }

    #pragma unroll
    for (int j = 0; j < QT3; j++) {
        int q = q0 + j;
        if (q < QD) out[(size_t)ch * QD + q] = acc[j];
    }
}

// ---------------- launch ------------------------------------------------------
extern "C" void kernel_launch(void* const* d_in, const int* in_sizes, int n_in,
                              void* d_out, int out_size) {
    const float* qk = (const float*)d_in[0];   // [1,64,30,54] -> [64][1620]
    const float* mk = (const float*)d_in[1];   // [1,64,32400] -> [64][32400]
    const float* mv = (const float*)d_in[2];   // [3,512,32400] -> [1536][32400]
    float* out = (float*)d_out;                // [3,1,512,30,54] -> [1536][1620]
    (void)in_sizes; (void)n_in; (void)out_size;

    k_asq<<<(MD + 255) / 256, 256>>>(mk);

    k_transpose<<<dim3((MD + 31) / 32, CHD / 32), dim3(32, 8)>>>(mv);

    size_t smem1 = (size_t)(CKD * MT + CKD * QT + MT + QT * 260) * sizeof(float); // 108032
    cudaFuncSetAttribute(k_aff_topk, cudaFuncAttributeMaxDynamicSharedMemorySize, (int)smem1);
    k_aff_topk<<<dim3(NQB, NCHUNK), 256, smem1>>>(qk, mk);

    k_merge_softmax<<<(QD + 255) / 256, 256>>>();

    k_readout<<<dim3((QD + QT3 - 1) / QT3, CHD / 256), 256>>>(out);
}

// round 3
// speedup vs baseline: 1.0985x; 1.0985x over previous
#include <cuda_runtime.h>
#include <math.h>
#include <stdint.h>

// Problem constants
#define CKD 64
#define QD 1620          // H*W = 30*54
#define OD 3
#define CVD 512
#define MD 32400
#define TOPK 20
#define CHD 1536         // OD*CVD

// K1 tiling
#define NCHUNK 11
#define CHUNK 2952       // ceil(MD/NCHUNK) rounded to 8; 11*2952 = 32472 >= 32400
#define QT 64            // q per K1 block
#define MT 256           // m tile per iteration
#define NQB 26           // ceil(QD/QT) -> 26*64 = 1664
#define ITERS 12         // ceil(CHUNK/MT)
#define CAP 32           // candidate buffer capacity per q per tile

// K3 tiling
#define QT3 16

// ---------------- device scratch (static globals, no allocation) -------------
__device__ float g_nasq[MD];                       // -0.125 * ||mk_m||^2
__device__ float g_vt[(size_t)MD * CHD];           // transposed mem_v [M][1536]
__device__ float g_pval[QD * NCHUNK * TOPK];       // per-chunk partial topk vals [q][chunk][20]
__device__ int   g_pidx[QD * NCHUNK * TOPK];       // per-chunk partial topk idx
__device__ float g_wval[QD * TOPK];                // softmax weights
__device__ int   g_widx[QD * TOPK];                // selected m indices

// ---------------- packed f32x2 helpers ---------------------------------------
__device__ __forceinline__ unsigned long long dup2(float v) {
    unsigned long long r;
    asm("mov.b64 %0, {%1, %1};" : "=l"(r) : "f"(v));
    return r;
}
__device__ __forceinline__ void ffma2(unsigned long long& d, unsigned long long a,
                                      unsigned long long b) {
    asm("fma.rn.f32x2 %0, %1, %2, %0;" : "+l"(d) : "l"(a), "l"(b));
}
__device__ __forceinline__ unsigned long long ffma2o(unsigned long long a,
                                                     unsigned long long b,
                                                     unsigned long long c) {
    unsigned long long d;
    asm("fma.rn.f32x2 %0, %1, %2, %3;" : "=l"(d) : "l"(a), "l"(b), "l"(c));
    return d;
}

// ---------------- K0: negated scaled a_sq precompute --------------------------
__global__ void k_asq(const float* __restrict__ mk) {
    int m = blockIdx.x * 256 + threadIdx.x;
    if (m >= MD) return;
    float s = 0.f;
    #pragma unroll
    for (int c = 0; c < CKD; c++) {
        float v = mk[c * MD + m];
        s += v * v;
    }
    g_nasq[m] = -(s * 0.125f);
}

// ---------------- KT: transpose mem_v [1536][M] -> v_t [M][1536] --------------
__global__ void k_transpose(const float* __restrict__ v) {
    __shared__ float tile[32][33];
    int m0 = blockIdx.x * 32;
    int c0 = blockIdx.y * 32;
    int tx = threadIdx.x, ty = threadIdx.y;  // 32 x 8
    #pragma unroll
    for (int i = ty; i < 32; i += 8) {
        int m = m0 + tx;
        int c = c0 + i;
        tile[i][tx] = (m < MD) ? v[(size_t)c * MD + m] : 0.f;
    }
    __syncthreads();
    #pragma unroll
    for (int i = ty; i < 32; i += 8) {
        int m = m0 + i;
        int c = c0 + tx;
        if (m < MD) g_vt[(size_t)m * CHD + c] = tile[tx][i];
    }
}

// ---------------- K1: fused affinity GEMM (FFMA2) + per-chunk top-20 ----------
// smem float offsets
#define S_AFFMK 0          // 16896 floats: mk tile (16384) UNION aff (64x264)
#define S_QK    16896      // 4096
#define S_NASQ  20992      // 256
#define S_LV    21248      // 64*20
#define S_LI    22528      // 64*20 (int)
#define S_SCV   23808      // 64*32
#define S_SCI   25856      // 64*32 (int)
#define S_SCNT  27904      // 64 (int)
#define S_TH    27968      // 64
#define S_TOTAL 28032      // floats -> 112128 bytes

__device__ __forceinline__ void list_insert(float* Lv, int* Li, float v, int mg) {
    // strict total order: larger value wins; equal value -> smaller index wins
    if (v > Lv[TOPK - 1] || (v == Lv[TOPK - 1] && mg < Li[TOPK - 1])) {
        int p = TOPK - 1;
        while (p > 0 && (v > Lv[p - 1] || (v == Lv[p - 1] && mg < Li[p - 1]))) {
            Lv[p] = Lv[p - 1]; Li[p] = Li[p - 1]; p--;
        }
        Lv[p] = v; Li[p] = mg;
    }
}

__global__ void __launch_bounds__(256, 2) k_aff_topk(
    const float* __restrict__ qk, const float* __restrict__ mk)
{
    extern __shared__ float smem[];
    float* affmk = smem + S_AFFMK;
    float* qks   = smem + S_QK;
    float* nasq  = smem + S_NASQ;
    float* lv    = smem + S_LV;
    int*   li    = (int*)(smem + S_LI);
    float* scv   = smem + S_SCV;
    int*   sci   = (int*)(smem + S_SCI);
    int*   scnt  = (int*)(smem + S_SCNT);
    float* th    = smem + S_TH;

    const int tid   = threadIdx.x;
    const int q0    = blockIdx.x * QT;
    const int chunk = blockIdx.y;
    const int mc0   = chunk * CHUNK;
    const int mcend = min(mc0 + CHUNK, MD);

    // init lists / gates / counters
    for (int i = tid; i < 64 * TOPK; i += 256) { lv[i] = -3.0e38f; li[i] = 0; }
    if (tid < 64) { scnt[tid] = 0; th[tid] = -3.0e38f; }

    // stage qk tile [64c][64q]
    for (int t = tid; t < CKD * QT; t += 256) {
        int c = t >> 6, j = t & 63;
        int q = q0 + j;
        qks[t] = (q < QD) ? qk[c * QD + q] : 0.f;
    }
    __syncthreads();

    const int tm = tid & 31, tq = tid >> 5;      // GEMM roles: 32 m-thr x 8 q-groups
    const int qown = tid >> 2, lane4 = tid & 3;  // scan roles: 64 q x 4 scanners

    for (int it = 0; it < ITERS; it++) {
        const int m_base = mc0 + it * MT;

        // stage mk tile [64c][256m] as float4 (coalesced) + negated asq
        {
            float4* mk4 = (float4*)affmk;
            #pragma unroll 4
            for (int t = tid; t < CKD * (MT / 4); t += 256) {
                int c = t >> 6, f4 = t & 63;
                int mg = m_base + (f4 << 2);
                float4 val = make_float4(0.f, 0.f, 0.f, 0.f);
                if (mg < MD) val = *(const float4*)(mk + (size_t)c * MD + mg);
                mk4[t] = val;  // float offset = c*256 + f4*4
            }
            int mg = m_base + tid;
            nasq[tid] = (mg < mcend) ? g_nasq[mg] : -1.0e37f;
        }
        __syncthreads();

        // packed-f32x2 register GEMM: 8 m (4 pairs) x 8 q per thread over c=0..63
        unsigned long long acc[8][4];
        #pragma unroll
        for (int i = 0; i < 8; i++) {
            #pragma unroll
            for (int j = 0; j < 4; j++) acc[i][j] = 0ull;
        }

        const float* mkbase = affmk + (tm << 2);
        const float* qbase  = qks + (tq << 3);
        #pragma unroll 4
        for (int c = 0; c < CKD; c++) {
            ulonglong2 a0 = *(const ulonglong2*)(mkbase + (c << 8));        // m pairs 0,1
            ulonglong2 a1 = *(const ulonglong2*)(mkbase + (c << 8) + 128);  // m pairs 2,3
            float4 qv0 = *(const float4*)(qbase + (c << 6));
            float4 qv1 = *(const float4*)(qbase + (c << 6) + 4);
            unsigned long long b[8];
            b[0] = dup2(qv0.x); b[1] = dup2(qv0.y); b[2] = dup2(qv0.z); b[3] = dup2(qv0.w);
            b[4] = dup2(qv1.x); b[5] = dup2(qv1.y); b[6] = dup2(qv1.z); b[7] = dup2(qv1.w);
            #pragma unroll
            for (int q = 0; q < 8; q++) {
                ffma2(acc[q][0], a0.x, b[q]);
                ffma2(acc[q][1], a0.y, b[q]);
                ffma2(acc[q][2], a1.x, b[q]);
                ffma2(acc[q][3], a1.y, b[q]);
            }
        }
        __syncthreads();  // all mk smem reads complete before aff overwrites region

        // epilogue: aff = 0.25*dot + (-0.125*asq), store [q][264] rows
        {
            ulonglong2 np0 = *(const ulonglong2*)(nasq + (tm << 2));
            ulonglong2 np1 = *(const ulonglong2*)(nasq + (tm << 2) + 128);
            unsigned long long c025 = dup2(0.25f);
            #pragma unroll
            for (int q = 0; q < 8; q++) {
                int qr = (tq << 3) + q;
                ulonglong2 s0, s1;
                s0.x = ffma2o(acc[q][0], c025, np0.x);
                s0.y = ffma2o(acc[q][1], c025, np0.y);
                s1.x = ffma2o(acc[q][2], c025, np1.x);
                s1.y = ffma2o(acc[q][3], c025, np1.y);
                *(ulonglong2*)(affmk + qr * 264 + (tm << 2)) = s0;
                *(ulonglong2*)(affmk + qr * 264 + (tm << 2) + 128) = s1;
            }
        }
        __syncthreads();

        // gated scan: push candidates above current 20th-best to per-q buffer
        {
            float gate = th[qown];
            const float* arow = affmk + qown * 264 + lane4;
            #pragma unroll 8
            for (int j = 0; j < 64; j++) {
                float v = arow[j << 2];
                if (v > gate) {
                    int pos = atomicAdd(&scnt[qown], 1);
                    if (pos < CAP) {
                        scv[qown * CAP + pos] = v;
                        sci[qown * CAP + pos] = m_base + lane4 + (j << 2);
                    }
                }
            }
        }
        __syncthreads();

        // merge candidates into per-q sorted top-20 (owner threads)
        if (tid < 64) {
            int n = scnt[tid];
            float* Lv = lv + tid * TOPK;
            int*   Li = li + tid * TOPK;
            if (n > CAP) {
                // overflow (always on tile 0): rescan the still-resident aff row
                const float* arow = affmk + tid * 264;
                for (int ml = 0; ml < MT; ml++) {
                    list_insert(Lv, Li, arow[ml], m_base + ml);
                }
            } else {
                for (int i2 = 0; i2 < n; i2++) {
                    list_insert(Lv, Li, scv[tid * CAP + i2], sci[tid * CAP + i2]);
                }
            }
            th[tid] = Lv[TOPK - 1];
            scnt[tid] = 0;
        }
        __syncthreads();
    }

    // writeout per-chunk partial lists, layout [q][chunk][20]
    if (tid < 64) {
        int q = q0 + tid;
        if (q < QD) {
            int ob = (q * NCHUNK + chunk) * TOPK;
            #pragma unroll
            for (int r = 0; r < TOPK; r++) {
                g_pval[ob + r] = lv[tid * TOPK + r];
                g_pidx[ob + r] = li[tid * TOPK + r];
            }
        }
    }
}

// ---------------- K2: merge chunk partials + softmax --------------------------
__global__ void k_merge_softmax() {
    int q = blockIdx.x * 128 + threadIdx.x;
    if (q >= QD) return;
    const float* pv = g_pval + (size_t)q * NCHUNK * TOPK;  // contiguous 880B per q
    const int*   pi = g_pidx + (size_t)q * NCHUNK * TOPK;
    int cur[NCHUNK];
    #pragma unroll
    for (int c = 0; c < NCHUNK; c++) cur[c] = 0;
    float vals[TOPK];
    int   idxs[TOPK];
    for (int r = 0; r < TOPK; r++) {
        float best = -3.4e38f;
        int bc = 0, bi = 0x7fffffff;
        #pragma unroll
        for (int c = 0; c < NCHUNK; c++) {
            if (cur[c] < TOPK) {
                float v = pv[c * TOPK + cur[c]];
                int  id = pi[c * TOPK + cur[c]];
                if (v > best || (v == best && id < bi)) { best = v; bc = c; bi = id; }
            }
        }
        vals[r] = best;
        idxs[r] = bi;
        cur[bc]++;
    }
    float mx = vals[0];  // merged list is descending
    float s = 0.f;
    #pragma unroll
    for (int r = 0; r < TOPK; r++) { vals[r] = expf(vals[r] - mx); s += vals[r]; }
    float inv = 1.f / s;
    #pragma unroll
    for (int r = 0; r < TOPK; r++) {
        g_wval[q * TOPK + r] = vals[r] * inv;
        g_widx[q * TOPK + r] = idxs[r];
    }
}

// ---------------- K3: sparse readout (coalesced gather on v_t) ----------------
__global__ void k_readout(float* __restrict__ out) {
    __shared__ float sw[QT3 * TOPK];
    __shared__ int   si[QT3 * TOPK];
    int q0 = blockIdx.x * QT3;
    int ch = blockIdx.y * 256 + threadIdx.x;
    for (int t = threadIdx.x; t < QT3 * TOPK; t += 256) {
        int q = q0 + t / TOPK;
        if (q < QD) {
            sw[t] = g_wval[q * TOPK + (t % TOPK)];
            si[t] = g_widx[q * TOPK + (t % TOPK)];
        } else {
            sw[t] = 0.f;
            si[t] = 0;
        }
    }
    __syncthreads();

    float acc[QT3];
    #pragma unroll
    for (int j = 0; j < QT3; j++) acc[j] = 0.f;

    #pragma unroll
    for (int k = 0; k < TOPK; k++) {
        #pragma unroll
        for (int j = 0; j < QT3; j++) {
            float w = sw[j * TOPK + k];
            int   m = si[j * TOPK + k];
            acc[j] += w * g_vt[(size_t)m * CHD + ch];
        }
    }

    #pragma unroll
    for (int j = 0; j < QT3; j++) {
        int q = q0 + j;
        if (q < QD) out[(size_t)ch * QD + q] = acc[j];
    }
}

// ---------------- launch ------------------------------------------------------
extern "C" void kernel_launch(void* const* d_in, const int* in_sizes, int n_in,
                              void* d_out, int out_size) {
    const float* qk = (const float*)d_in[0];   // [1,64,30,54] -> [64][1620]
    const float* mk = (const float*)d_in[1];   // [1,64,32400] -> [64][32400]
    const float* mv = (const float*)d_in[2];   // [3,512,32400] -> [1536][32400]
    float* out = (float*)d_out;                // [3,1,512,30,54] -> [1536][1620]
    (void)in_sizes; (void)n_in; (void)out_size;

    k_asq<<<(MD + 255) / 256, 256>>>(mk);

    k_transpose<<<dim3((MD + 31) / 32, CHD / 32), dim3(32, 8)>>>(mv);

    size_t smem1 = (size_t)S_TOTAL * sizeof(float);  // 112128 bytes
    cudaFuncSetAttribute(k_aff_topk, cudaFuncAttributeMaxDynamicSharedMemorySize, (int)smem1);
    k_aff_topk<<<dim3(NQB, NCHUNK), 256, smem1>>>(qk, mk);

    k_merge_softmax<<<(QD + 127) / 128, 128>>>();

    k_readout<<<dim3((QD + QT3 - 1) / QT3, CHD / 256), 256>>>(out);
}